// round 16
// baseline (speedup 1.0000x reference)
#include <cuda_runtime.h>
#include <cstdint>

// Masked cumsum along dim 1: out[b,:] = cumsum(where(mask, x, 0))
// B=256 rows, N=131072 cols, fp32 x, int32 mask.
//
// R13: R5 machinery with HALF the rendezvous count. Iteration = 8192 elems
// as two staggered 4096-elem sub-chunks (A, B): each phase consumes its regs,
// issues its OWN next-iter loads (4x LDG.128 -> MLP_p1 stays 4, unlike R8's
// front-batched 8), does lane+warp scans, folds lexcl/round offsets into the
// values (cuts live regs), STS's its warp total. ONE __syncthreads; then the
// two CTA scans over 16-wide total vectors run as 2-wide ILP shfl chains;
// bases derived; carry advanced once; 4 coalesced STG.128.
// 16 iterations/row instead of 32 -> per-byte barrier+CTA-scan+carry cost
// halved. Double-buffered shW removes the trailing barrier.

#define CS_THREADS 512
#define CS_NWARPS  16
#define CS_CHUNK   8192                   // per iteration (A + B)
#define CS_NCOLS   131072
#define CS_ITERS   (CS_NCOLS / CS_CHUNK)  // 16

__global__ __launch_bounds__(CS_THREADS, 2)
void masked_cumsum_kernel(const float* __restrict__ x,
                          const int* __restrict__ mask,
                          float* __restrict__ out) {
    __shared__ float shW[2][2][CS_NWARPS];  // [iterbuf][sub][warp] totals

    const int row = blockIdx.x;
    const size_t roff4 = (size_t)row * (CS_NCOLS / 4);
    const float4* __restrict__ x4 = reinterpret_cast<const float4*>(x) + roff4;
    const int4*   __restrict__ m4 = reinterpret_cast<const int4*>(mask) + roff4;
    float4*       __restrict__ o4 = reinterpret_cast<float4*>(out) + roff4;

    const int tid  = threadIdx.x;
    const int lane = tid & 31;
    const int warp = tid >> 5;
    const int wbase = warp * 64 + lane;   // f4 index within a sub-chunk

    float carry = 0.0f;
    float sA[8], sB[8];                   // folded values awaiting base

    // Prefetch iteration 0 (A at +0, B at +1024 f4)
    float4 pxA0 = __ldcs(&x4[wbase]);
    float4 pxA1 = __ldcs(&x4[wbase + 32]);
    int4   pmA0 = __ldcs(&m4[wbase]);
    int4   pmA1 = __ldcs(&m4[wbase + 32]);
    float4 pxB0 = __ldcs(&x4[1024 + wbase]);
    float4 pxB1 = __ldcs(&x4[1024 + wbase + 32]);
    int4   pmB0 = __ldcs(&m4[1024 + wbase]);
    int4   pmB1 = __ldcs(&m4[1024 + wbase + 32]);

    for (int it = 0; it < CS_ITERS; ++it) {
        const int ibase = it * (CS_CHUNK / 4);
        const int nbase = ibase + (CS_CHUNK / 4);
        const bool more = (it + 1 < CS_ITERS);
        const int buf = it & 1;

        // ================= A phase =================
        {
            const float4 xa0 = pxA0, xa1 = pxA1;
            const int4   ma0 = pmA0, ma1 = pmA1;
            if (more) {
                pxA0 = __ldcs(&x4[nbase + wbase]);
                pxA1 = __ldcs(&x4[nbase + wbase + 32]);
                pmA0 = __ldcs(&m4[nbase + wbase]);
                pmA1 = __ldcs(&m4[nbase + wbase + 32]);
            }
            float v0 = ma0.x ? xa0.x : 0.f, v1 = ma0.y ? xa0.y : 0.f;
            float v2 = ma0.z ? xa0.z : 0.f, v3 = ma0.w ? xa0.w : 0.f;
            float u0 = ma1.x ? xa1.x : 0.f, u1 = ma1.y ? xa1.y : 0.f;
            float u2 = ma1.z ? xa1.z : 0.f, u3 = ma1.w ? xa1.w : 0.f;
            v1 += v0; v2 += v1; v3 += v2;
            u1 += u0; u2 += u1; u3 += u2;
            float ia = v3, ib = u3;
            #pragma unroll
            for (int d = 1; d < 32; d <<= 1) {
                float na = __shfl_up_sync(0xffffffffu, ia, d);
                float nb = __shfl_up_sync(0xffffffffu, ib, d);
                if (lane >= d) { ia += na; ib += nb; }
            }
            const float le0 = ia - v3;
            const float T0  = __shfl_sync(0xffffffffu, ia, 31);
            const float le1 = (ib - u3) + T0;
            const float T1  = __shfl_sync(0xffffffffu, ib, 31);
            sA[0] = v0 + le0; sA[1] = v1 + le0; sA[2] = v2 + le0; sA[3] = v3 + le0;
            sA[4] = u0 + le1; sA[5] = u1 + le1; sA[6] = u2 + le1; sA[7] = u3 + le1;
            if (lane == 0) shW[buf][0][warp] = T0 + T1;
        }

        // ================= B phase =================
        {
            const float4 xb0 = pxB0, xb1 = pxB1;
            const int4   mb0 = pmB0, mb1 = pmB1;
            if (more) {
                pxB0 = __ldcs(&x4[nbase + 1024 + wbase]);
                pxB1 = __ldcs(&x4[nbase + 1024 + wbase + 32]);
                pmB0 = __ldcs(&m4[nbase + 1024 + wbase]);
                pmB1 = __ldcs(&m4[nbase + 1024 + wbase + 32]);
            }
            float v0 = mb0.x ? xb0.x : 0.f, v1 = mb0.y ? xb0.y : 0.f;
            float v2 = mb0.z ? xb0.z : 0.f, v3 = mb0.w ? xb0.w : 0.f;
            float u0 = mb1.x ? xb1.x : 0.f, u1 = mb1.y ? xb1.y : 0.f;
            float u2 = mb1.z ? xb1.z : 0.f, u3 = mb1.w ? xb1.w : 0.f;
            v1 += v0; v2 += v1; v3 += v2;
            u1 += u0; u2 += u1; u3 += u2;
            float ia = v3, ib = u3;
            #pragma unroll
            for (int d = 1; d < 32; d <<= 1) {
                float na = __shfl_up_sync(0xffffffffu, ia, d);
                float nb = __shfl_up_sync(0xffffffffu, ib, d);
                if (lane >= d) { ia += na; ib += nb; }
            }
            const float le0 = ia - v3;
            const float T0  = __shfl_sync(0xffffffffu, ia, 31);
            const float le1 = (ib - u3) + T0;
            const float T1  = __shfl_sync(0xffffffffu, ib, 31);
            sB[0] = v0 + le0; sB[1] = v1 + le0; sB[2] = v2 + le0; sB[3] = v3 + le0;
            sB[4] = u0 + le1; sB[5] = u1 + le1; sB[6] = u2 + le1; sB[7] = u3 + le1;
            if (lane == 0) shW[buf][1][warp] = T0 + T1;
        }

        __syncthreads();

        // ============ CTA phase: two ILP scans of 16 totals ============
        float wA = (lane < CS_NWARPS) ? shW[buf][0][lane] : 0.f;
        float wB = (lane < CS_NWARPS) ? shW[buf][1][lane] : 0.f;
        float iA = wA, iB = wB;
        #pragma unroll
        for (int d = 1; d < CS_NWARPS; d <<= 1) {
            float nA = __shfl_up_sync(0xffffffffu, iA, d);
            float nB = __shfl_up_sync(0xffffffffu, iB, d);
            if (lane >= d) { iA += nA; iB += nB; }
        }
        const float wexclA = __shfl_sync(0xffffffffu, iA, warp) -
                             __shfl_sync(0xffffffffu, wA, warp);
        const float totalA = __shfl_sync(0xffffffffu, iA, CS_NWARPS - 1);
        const float wexclB = __shfl_sync(0xffffffffu, iB, warp) -
                             __shfl_sync(0xffffffffu, wB, warp);
        const float totalB = __shfl_sync(0xffffffffu, iB, CS_NWARPS - 1);

        const float baseA = carry + wexclA;
        const float baseB = carry + totalA + wexclB;
        carry += totalA + totalB;

        float4 o;
        o.x = sA[0] + baseA; o.y = sA[1] + baseA; o.z = sA[2] + baseA; o.w = sA[3] + baseA;
        __stcs(&o4[ibase + wbase], o);
        o.x = sA[4] + baseA; o.y = sA[5] + baseA; o.z = sA[6] + baseA; o.w = sA[7] + baseA;
        __stcs(&o4[ibase + wbase + 32], o);
        o.x = sB[0] + baseB; o.y = sB[1] + baseB; o.z = sB[2] + baseB; o.w = sB[3] + baseB;
        __stcs(&o4[ibase + 1024 + wbase], o);
        o.x = sB[4] + baseB; o.y = sB[5] + baseB; o.z = sB[6] + baseB; o.w = sB[7] + baseB;
        __stcs(&o4[ibase + 1024 + wbase + 32], o);
        // No trailing barrier: shW double-buffered across iterations.
    }
}

extern "C" void kernel_launch(void* const* d_in, const int* in_sizes, int n_in,
                              void* d_out, int out_size) {
    const float* x    = (const float*)d_in[0];
    const int*   mask = (const int*)d_in[1];
    float*       out  = (float*)d_out;
    const int rows = out_size / CS_NCOLS;   // 256
    masked_cumsum_kernel<<<rows, CS_THREADS>>>(x, mask, out);
}

// round 17
// speedup vs baseline: 1.0745x; 1.0745x over previous
#include <cuda_runtime.h>
#include <cstdint>

// Masked cumsum along dim 1: out[b,:] = cumsum(where(mask, x, 0))
// B=256 rows, N=131072 cols, fp32 x, int32 mask.
//
// FINAL (R5 config, measured best: 63.3us, DRAM 80.1%, ~7.0 TB/s effective
// counting L2-resident dirty output lines).
// One persistent CTA per row, serial carry over 32 chunks of 4096. Each warp
// owns a contiguous 256-float segment per chunk (2 rounds of lane-consecutive
// float4/int4 -> every LDG/STG.128 is a perfect 4-line access). One-chunk-
// ahead register prefetch (MLP_p1=4); streaming cache hints (single-touch).
// ONE barrier per iteration: after it, every warp redundantly loads all 16
// warp totals from smem (broadcast, conflict-free) and scans them itself
// (4 shfl steps) for its exclusive prefix + chunk total. Double-buffered smem
// removes the trailing barrier (iter i's reads of buf are fenced from iter
// i+2's writes by iter i+1's barrier).
//
// Rejected by measurement this session (all vs 63.3us): decoupled lookback
// 110us; chained tiles 95us; scalar CTA-scan tree 66us; mbarrier lag-1
// pipeline 66us; 8192-elem chunks (front-batched 69us, staggered 68us @ the
// 64-reg occ-2 wall); 128-thread CTAs 96us; cp.async 3-stage pipeline 72us.

#define CS_THREADS 512
#define CS_NWARPS  16
#define CS_CHUNK   4096                   // 512 thr * 8 elems
#define CS_NCOLS   131072
#define CS_ITERS   (CS_NCOLS / CS_CHUNK)  // 32

__device__ __forceinline__ float warp_incl_scan(float v, int lane) {
    #pragma unroll
    for (int d = 1; d < 32; d <<= 1) {
        float n = __shfl_up_sync(0xffffffffu, v, d);
        if (lane >= d) v += n;
    }
    return v;
}

__global__ __launch_bounds__(CS_THREADS, 2)
void masked_cumsum_kernel(const float* __restrict__ x,
                          const int* __restrict__ mask,
                          float* __restrict__ out) {
    __shared__ float sh[2][CS_NWARPS];   // [buf][w] = warp w's chunk total

    const int row = blockIdx.x;
    const size_t roff4 = (size_t)row * (CS_NCOLS / 4);
    const float4* __restrict__ x4 = reinterpret_cast<const float4*>(x) + roff4;
    const int4*   __restrict__ m4 = reinterpret_cast<const int4*>(mask) + roff4;
    float4*       __restrict__ o4 = reinterpret_cast<float4*>(out) + roff4;

    const int tid  = threadIdx.x;
    const int lane = tid & 31;
    const int warp = tid >> 5;
    // Warp w owns floats [w*256, w*256+256) of each chunk:
    // round r (0,1), lane l -> float4 index w*64 + r*32 + l (perfectly coalesced)
    const int wbase = warp * 64 + lane;

    float carry = 0.0f;

    // Prefetch chunk 0
    float4 pa0 = __ldcs(&x4[wbase]);
    float4 pa1 = __ldcs(&x4[wbase + 32]);
    int4   pm0 = __ldcs(&m4[wbase]);
    int4   pm1 = __ldcs(&m4[wbase + 32]);

    for (int it = 0; it < CS_ITERS; ++it) {
        const float4 xa0 = pa0, xa1 = pa1;
        const int4   ma0 = pm0, ma1 = pm1;
        // Issue next chunk's loads immediately; consumed next iteration.
        if (it + 1 < CS_ITERS) {
            const int nb = (it + 1) * (CS_CHUNK / 4) + wbase;
            pa0 = __ldcs(&x4[nb]);
            pa1 = __ldcs(&x4[nb + 32]);
            pm0 = __ldcs(&m4[nb]);
            pm1 = __ldcs(&m4[nb + 32]);
        }

        // Apply mask (each int32 is 0 or 1)
        float v[2][4];
        v[0][0] = ma0.x ? xa0.x : 0.f; v[0][1] = ma0.y ? xa0.y : 0.f;
        v[0][2] = ma0.z ? xa0.z : 0.f; v[0][3] = ma0.w ? xa0.w : 0.f;
        v[1][0] = ma1.x ? xa1.x : 0.f; v[1][1] = ma1.y ? xa1.y : 0.f;
        v[1][2] = ma1.z ? xa1.z : 0.f; v[1][3] = ma1.w ? xa1.w : 0.f;

        // Lane-local inclusive scans (2 independent rounds -> ILP)
        #pragma unroll
        for (int b = 0; b < 2; ++b)
            #pragma unroll
            for (int i = 1; i < 4; ++i) v[b][i] += v[b][i - 1];

        // Warp scan per round (two independent shfl chains), chain round totals
        float lexcl[2], T[2];
        #pragma unroll
        for (int b = 0; b < 2; ++b) {
            const float s = v[b][3];
            const float incl = warp_incl_scan(s, lane);
            lexcl[b] = incl - s;
            T[b] = __shfl_sync(0xffffffffu, incl, 31);
        }
        const float warpTotal = T[0] + T[1];

        const int buf = it & 1;
        if (lane == 0) sh[buf][warp] = warpTotal;
        __syncthreads();

        // Every warp redundantly scans the 16 warp totals (smem broadcast read,
        // 4-step shfl prefix over lanes 0..15). No second barrier, no warp0 wait.
        float w = (lane < CS_NWARPS) ? sh[buf][lane] : 0.f;
        float wincl = w;
        #pragma unroll
        for (int d = 1; d < CS_NWARPS; d <<= 1) {
            float n = __shfl_up_sync(0xffffffffu, wincl, d);
            if (lane >= d) wincl += n;
        }
        const float wexcl      = __shfl_sync(0xffffffffu, wincl, warp) -
                                 __shfl_sync(0xffffffffu, w,     warp);
        const float chunkTotal = __shfl_sync(0xffffffffu, wincl, CS_NWARPS - 1);

        const float base0 = carry + wexcl;
        carry += chunkTotal;

        const float baseA = base0 + lexcl[0];
        const float baseB = base0 + T[0] + lexcl[1];
        const int ob = it * (CS_CHUNK / 4) + wbase;
        float4 oa, obv;
        oa.x  = v[0][0] + baseA; oa.y  = v[0][1] + baseA;
        oa.z  = v[0][2] + baseA; oa.w  = v[0][3] + baseA;
        obv.x = v[1][0] + baseB; obv.y = v[1][1] + baseB;
        obv.z = v[1][2] + baseB; obv.w = v[1][3] + baseB;
        __stcs(&o4[ob],      oa);
        __stcs(&o4[ob + 32], obv);
        // No trailing barrier: iter i+2's STS to this buf is fenced by iter i+1's bar.
    }
}

extern "C" void kernel_launch(void* const* d_in, const int* in_sizes, int n_in,
                              void* d_out, int out_size) {
    const float* x    = (const float*)d_in[0];
    const int*   mask = (const int*)d_in[1];
    float*       out  = (float*)d_out;
    const int rows = out_size / CS_NCOLS;   // 256
    masked_cumsum_kernel<<<rows, CS_THREADS>>>(x, mask, out);
}